// round 12
// baseline (speedup 1.0000x reference)
#include <cuda_runtime.h>
#include <cuda_fp16.h>
#include <math.h>

#define L    384
#define DP   128
#define NH   4
#define DH   32
#define LL   (L*L)            // 147456
#define SPLIT 8
#define NSPL  (L/SPLIT)       // 48
#define ND   (L*DH)           // 12288

// ---------------- scratch ----------------
__device__ __align__(16) __half g_qh [NH*LL*DH];     // q fp16: ((h*L+n)*L+i)*32+d
__device__ __align__(16) __half g_kh [NH*LL*DH];     // k fp16: ((h*L+n)*L+j)*32+d
__device__ __align__(16) __half g_vh [NH*(size_t)L*ND]; // v fp16 NATURAL: (h*L+j)*12288 + n*32+d
__device__ __align__(16) __half g_gateh[LL*DP];      // fp16 gate
__device__ __align__(16) __half g_oh [LL*DP];        // gated fp16, row n*L+i
__device__ __align__(16) __half g_attnh[NH*LL];      // softmax probs fp16 [h][i][j]
__device__ __align__(16) float  g_battn[NH*LL];      // [h][i][j]
__device__ __align__(16) float  g_qkp [SPLIT*NH*LL]; // qk partials [s][h][i][j]
__device__ __align__(16) __half g_w4T [4*DP*DP];     // fp16 TRANSPOSED: [which][n][k]
__device__ __align__(16) __half g_woutT[DP*DP];      // fp16 TRANSPOSED: [n][k]

// ---------------- helpers ----------------
__device__ __forceinline__ void cpa16(void* dst, const void* src) {
    unsigned d = (unsigned)__cvta_generic_to_shared(dst);
    asm volatile("cp.async.cg.shared.global [%0], [%1], 16;\n" :: "r"(d), "l"(src));
}
#define CPA_COMMIT asm volatile("cp.async.commit_group;\n" ::: "memory")
#define CPA_WAIT0  asm volatile("cp.async.wait_group 0;\n" ::: "memory")

__device__ __forceinline__ void mma16(float c[4], const unsigned a[4], const unsigned b[2]) {
    asm volatile(
        "mma.sync.aligned.m16n8k16.row.col.f32.f16.f16.f32 "
        "{%0,%1,%2,%3},{%4,%5,%6,%7},{%8,%9},{%0,%1,%2,%3};\n"
        : "+f"(c[0]), "+f"(c[1]), "+f"(c[2]), "+f"(c[3])
        : "r"(a[0]), "r"(a[1]), "r"(a[2]), "r"(a[3]), "r"(b[0]), "r"(b[1]));
}
#define LDSM4(r0,r1,r2,r3,addr) \
    asm volatile("ldmatrix.sync.aligned.m8n8.x4.shared.b16 {%0,%1,%2,%3}, [%4];" \
                 : "=r"(r0), "=r"(r1), "=r"(r2), "=r"(r3) : "r"(addr))
#define LDSM4T(r0,r1,r2,r3,addr) \
    asm volatile("ldmatrix.sync.aligned.m8n8.x4.trans.shared.b16 {%0,%1,%2,%3}, [%4];" \
                 : "=r"(r0), "=r"(r1), "=r"(r2), "=r"(r3) : "r"(addr))

// ---------------- kernel 0: transpose + fp16-convert weights ----------------
__global__ __launch_bounds__(256) void k_prep(const float* __restrict__ Wq,
                                              const float* __restrict__ Wk,
                                              const float* __restrict__ Wv,
                                              const float* __restrict__ Wg,
                                              const float* __restrict__ Wout)
{
    int id = blockIdx.x * 256 + threadIdx.x;     // 81920
    if (id < 4*DP*DP) {
        int which = id >> 14, rem = id & (DP*DP - 1);
        int n = rem >> 7, k = rem & 127;
        const float* W = (which==0) ? Wq : (which==1) ? Wk : (which==2) ? Wv : Wg;
        g_w4T[id] = __float2half(W[k*DP + n]);
    } else {
        int rem = id - 4*DP*DP;
        int n = rem >> 7, k = rem & 127;
        g_woutT[rem] = __float2half(Wout[k*DP + n]);
    }
}

// ---------------- kernel 2: bias path ----------------
__global__ __launch_bounds__(256) void k_bias(const float* __restrict__ bias,
                                              const float* __restrict__ gamma,
                                              const float* __restrict__ beta,
                                              const float* __restrict__ Wb)
{
    int warp = (blockIdx.x * blockDim.x + threadIdx.x) >> 5;
    int lane = threadIdx.x & 31;
    if (warp >= LL) return;
    int j = warp / L, i = warp % L;
    float4 x = ((const float4*)(bias + (size_t)warp * DP))[lane];
    float s  = x.x + x.y + x.z + x.w;
    float ss = x.x*x.x + x.y*x.y + x.z*x.z + x.w*x.w;
    #pragma unroll
    for (int o = 16; o; o >>= 1) {
        s  += __shfl_xor_sync(0xffffffffu, s,  o);
        ss += __shfl_xor_sync(0xffffffffu, ss, o);
    }
    float mean = s * (1.0f/DP);
    float var  = ss * (1.0f/DP) - mean*mean;
    float inv  = rsqrtf(var + 1e-5f);
    float4 g = ((const float4*)gamma)[lane];
    float4 b = ((const float4*)beta )[lane];
    float y[4];
    y[0] = (x.x - mean)*inv*g.x + b.x;
    y[1] = (x.y - mean)*inv*g.y + b.y;
    y[2] = (x.z - mean)*inv*g.z + b.z;
    y[3] = (x.w - mean)*inv*g.w + b.w;
    float acc[NH] = {0.f, 0.f, 0.f, 0.f};
    #pragma unroll
    for (int t = 0; t < 4; t++) {
        int c = lane*4 + t;
        #pragma unroll
        for (int h = 0; h < NH; h++)
            acc[h] += y[t] * Wb[c*NH + h];
    }
    #pragma unroll
    for (int h = 0; h < NH; h++)
        #pragma unroll
        for (int o = 16; o; o >>= 1)
            acc[h] += __shfl_xor_sync(0xffffffffu, acc[h], o);
    if (lane == 0) {
        #pragma unroll
        for (int h = 0; h < NH; h++)
            g_battn[(size_t)h*LL + (size_t)i*L + j] = acc[h];
    }
}

// ---------------- kernel 3: fused LN + 4 projections, fp16 MMA ----------------
__global__ __launch_bounds__(256, 2) void k_projf(const float* __restrict__ pair,
                                                  const float* __restrict__ gamma,
                                                  const float* __restrict__ beta,
                                                  const float* __restrict__ bg)
{
    extern __shared__ char smraw[];
    __half (*Ah)[136] = (__half(*)[136])smraw;
    char* warea = smraw + 128*136*2;
    float (*Pf)[132]      = (float(*)[132])warea;
    __half (*Wh)[128][136] = (__half(*)[128][136])warea;

    int m0 = blockIdx.x * 128;
    int n  = m0 / L;
    int i0 = m0 % L;
    int tid = threadIdx.x;
    int w = tid >> 5, lane = tid & 31;
    int wm = w >> 1, wn = w & 1;        // 4m x 2n warps, 32x64 tiles
    int lrow = lane >> 2, lq = lane & 3;

    #pragma unroll
    for (int it = 0; it < 16; it++) {
        int cid = tid + it*256;
        int row = cid >> 5, part = cid & 31;
        cpa16(&Pf[row][part*4], pair + ((size_t)(i0+row)*L + n)*DP + part*4);
    }
    CPA_COMMIT; CPA_WAIT0; __syncthreads();

    // LN -> fp16 A tile
    {
        float4 gm = ((const float4*)gamma)[lane];
        float4 bt = ((const float4*)beta )[lane];
        #pragma unroll
        for (int r = 0; r < 16; r++) {
            int row = w*16 + r;
            float4 x = *(float4*)&Pf[row][lane*4];
            float s  = x.x + x.y + x.z + x.w;
            float ss = x.x*x.x + x.y*x.y + x.z*x.z + x.w*x.w;
            #pragma unroll
            for (int o = 16; o; o >>= 1) {
                s  += __shfl_xor_sync(0xffffffffu, s,  o);
                ss += __shfl_xor_sync(0xffffffffu, ss, o);
            }
            float mean = s * (1.0f/DP);
            float var  = ss * (1.0f/DP) - mean*mean;
            float inv  = rsqrtf(var + 1e-5f);
            __half2 h01 = __floats2half2_rn((x.x - mean)*inv*gm.x + bt.x,
                                            (x.y - mean)*inv*gm.y + bt.y);
            __half2 h23 = __floats2half2_rn((x.z - mean)*inv*gm.z + bt.z,
                                            (x.w - mean)*inv*gm.w + bt.w);
            *(__half2*)&Ah[row][lane*4]   = h01;
            *(__half2*)&Ah[row][lane*4+2] = h23;
        }
    }
    __syncthreads();

    unsigned aBase = (unsigned)__cvta_generic_to_shared(&Ah[0][0]);
    unsigned aLane = (unsigned)((lane & 15)*272 + ((lane >> 4) & 1)*16);
    unsigned bLane = (unsigned)((((lane >> 4) & 1)*8 + (lane & 7))*272 + ((lane >> 3) & 1)*16);

    auto loadW = [&](int buf, int which) {
        #pragma unroll
        for (int it = 0; it < 8; it++) {
            int cid = tid + it*256;
            int row = cid >> 4, part = cid & 15;
            cpa16(&Wh[buf][row][part*8],
                  g_w4T + (size_t)which*DP*DP + (size_t)row*DP + part*8);
        }
    };
    loadW(0, 0); CPA_COMMIT;

    const float qscale = 0.17677669529663689f;
    const float kscale = 1.0f / (float)L;

    for (int which = 0; which < 4; which++) {
        CPA_WAIT0; __syncthreads();
        if (which < 3) { loadW((which+1)&1, which+1); CPA_COMMIT; }
        int buf = which & 1;
        unsigned wBase = (unsigned)__cvta_generic_to_shared(&Wh[buf][0][0]);

        float acc[2][8][4];
        #pragma unroll
        for (int mt = 0; mt < 2; mt++)
            #pragma unroll
            for (int nt = 0; nt < 8; nt++)
                #pragma unroll
                for (int r = 0; r < 4; r++) acc[mt][nt][r] = 0.f;

        #pragma unroll
        for (int ks = 0; ks < 8; ks++) {
            unsigned a[2][4], b[8][2];
            #pragma unroll
            for (int mt = 0; mt < 2; mt++) {
                unsigned addr = aBase + (unsigned)((wm*32 + mt*16)*272 + ks*32) + aLane;
                LDSM4(a[mt][0], a[mt][1], a[mt][2], a[mt][3], addr);
            }
            #pragma unroll
            for (int np = 0; np < 4; np++) {
                unsigned addr = wBase + (unsigned)((wn*64 + np*16)*272 + ks*32) + bLane;
                LDSM4(b[2*np][0], b[2*np][1], b[2*np+1][0], b[2*np+1][1], addr);
            }
            #pragma unroll
            for (int mt = 0; mt < 2; mt++)
                #pragma unroll
                for (int nt = 0; nt < 8; nt++)
                    mma16(acc[mt][nt], a[mt], b[nt]);
        }

        // epilogue
        #pragma unroll
        for (int mt = 0; mt < 2; mt++) {
            #pragma unroll
            for (int hf = 0; hf < 2; hf++) {
                int i = i0 + wm*32 + mt*16 + lrow + hf*8;
                #pragma unroll
                for (int nt = 0; nt < 8; nt++) {
                    int cc = wn*64 + nt*8 + 2*lq;
                    float v0 = acc[mt][nt][hf*2+0];
                    float v1 = acc[mt][nt][hf*2+1];
                    if (which == 0) {
                        int h = cc >> 5, d = cc & 31;
                        *(__half2*)(g_qh + ((size_t)(h*L+n)*L + i)*DH + d) =
                            __floats2half2_rn(v0*qscale, v1*qscale);
                    } else if (which == 1) {
                        int h = cc >> 5, d = cc & 31;
                        *(__half2*)(g_kh + ((size_t)(h*L+n)*L + i)*DH + d) =
                            __floats2half2_rn(v0*kscale, v1*kscale);
                    } else if (which == 2) {
                        int h = cc >> 5, d = cc & 31;   // i is j here
                        *(__half2*)(g_vh + ((size_t)(h*L) + i)*ND + n*DH + d) =
                            __floats2half2_rn(v0, v1);
                    } else {
                        v0 = 1.0f/(1.0f + expf(-(v0 + bg[cc  ])));
                        v1 = 1.0f/(1.0f + expf(-(v1 + bg[cc+1])));
                        *(__half2*)(g_gateh + ((size_t)(n*L+i))*DP + cc) =
                            __floats2half2_rn(v0, v1);
                    }
                }
            }
        }
    }
}

// ---------------- kernel 4: QK logits, fp16 MMA + ldmatrix ----------------
__global__ __launch_bounds__(256, 2) void k_qk()
{
    extern __shared__ __half smh[];
    __half* Qs = smh;                   // [2 st][2 n2][128][40]
    __half* Ks = smh + 2*2*128*40;
    int i0 = blockIdx.x * 128, j0 = blockIdx.y * 128;
    int h = blockIdx.z & 3, s = blockIdx.z >> 2;
    int tid = threadIdx.x;
    int w = tid >> 5, lane = tid & 31;
    int wm = w >> 1, wn = w & 1;
    int lrow = lane >> 2, lq = lane & 3;
    const __half* Qg = g_qh + (size_t)h*L*L*DH;
    const __half* Kg = g_kh + (size_t)h*L*L*DH;

    unsigned qBase = (unsigned)__cvta_generic_to_shared(Qs);
    unsigned kBase = (unsigned)__cvta_generic_to_shared(Ks);
    unsigned aLane = (unsigned)((lane & 15)*80 + ((lane >> 4) & 1)*16);
    unsigned bLane = (unsigned)((((lane >> 4) & 1)*8 + (lane & 7))*80 + ((lane >> 3) & 1)*16);

    auto load = [&](int st, int n) {
        #pragma unroll
        for (int it = 0; it < 4; it++) {
            int cid = tid + it*256;
            int n2 = cid >> 9, rem = cid & 511;
            int row = rem >> 2, part = rem & 3;
            cpa16(Qs + ((st*2 + n2)*128 + row)*40 + part*8,
                  Qg + ((size_t)(n+n2)*L + i0 + row)*DH + part*8);
        }
        #pragma unroll
        for (int it = 0; it < 4; it++) {
            int cid = tid + it*256;
            int n2 = cid >> 9, rem = cid & 511;
            int row = rem >> 2, part = rem & 3;
            cpa16(Ks + ((st*2 + n2)*128 + row)*40 + part*8,
                  Kg + ((size_t)(n+n2)*L + j0 + row)*DH + part*8);
        }
    };

    float acc[2][8][4];
    #pragma unroll
    for (int mt = 0; mt < 2; mt++)
        #pragma unroll
        for (int nt = 0; nt < 8; nt++)
            #pragma unroll
            for (int r = 0; r < 4; r++) acc[mt][nt][r] = 0.f;

    load(0, s*NSPL); CPA_COMMIT;
    const int IT = NSPL/2;
    for (int it = 0; it < IT; it++) {
        CPA_WAIT0; __syncthreads();
        if (it+1 < IT) { load((it+1)&1, s*NSPL + (it+1)*2); CPA_COMMIT; }
        int st = it & 1;
        #pragma unroll
        for (int n2 = 0; n2 < 2; n2++) {
            unsigned qTile = qBase + (unsigned)((st*2 + n2)*128*80);
            unsigned kTile = kBase + (unsigned)((st*2 + n2)*128*80);
            #pragma unroll
            for (int ks = 0; ks < 2; ks++) {
                unsigned a[2][4], b[8][2];
                #pragma unroll
                for (int mt = 0; mt < 2; mt++) {
                    unsigned addr = qTile + (unsigned)((wm*32 + mt*16)*80 + ks*32) + aLane;
                    LDSM4(a[mt][0], a[mt][1], a[mt][2], a[mt][3], addr);
                }
                #pragma unroll
                for (int np = 0; np < 4; np++) {
                    unsigned addr = kTile + (unsigned)((wn*64 + np*16)*80 + ks*32) + bLane;
                    LDSM4(b[2*np][0], b[2*np][1], b[2*np+1][0], b[2*np+1][1], addr);
                }
                #pragma unroll
                for (int mt = 0; mt < 2; mt++)
                    #pragma unroll
                    for (int nt = 0; nt < 8; nt++)
                        mma16(acc[mt][nt], a[mt], b[nt]);
            }
        }
    }
    float* dst = g_qkp + (size_t)(s*NH + h)*LL;
    #pragma unroll
    for (int mt = 0; mt < 2; mt++)
        #pragma unroll
        for (int hf = 0; hf < 2; hf++) {
            int i = i0 + wm*32 + mt*16 + lrow + hf*8;
            #pragma unroll
            for (int nt = 0; nt < 8; nt++) {
                int j = j0 + wn*64 + nt*8 + 2*lq;
                *(float2*)(dst + (size_t)i*L + j) =
                    make_float2(acc[mt][nt][hf*2], acc[mt][nt][hf*2+1]);
            }
        }
}

// ---------------- kernel 5: softmax -> fp16 probs ----------------
__global__ __launch_bounds__(128) void k_softmax()
{
    __shared__ float redm[4], reds[4];
    int i = blockIdx.x, h = blockIdx.y;
    int tid = threadIdx.x;
    float v[3];
    float mx = -1e30f;
    #pragma unroll
    for (int r = 0; r < 3; r++) {
        int j = tid + r*128;
        float a = g_battn[(size_t)h*LL + (size_t)i*L + j];
        #pragma unroll
        for (int s = 0; s < SPLIT; s++)
            a += g_qkp[(size_t)(s*NH + h)*LL + (size_t)i*L + j];
        v[r] = a;
        mx = fmaxf(mx, a);
    }
    #pragma unroll
    for (int o = 16; o; o >>= 1) mx = fmaxf(mx, __shfl_xor_sync(0xffffffffu, mx, o));
    if ((tid & 31) == 0) redm[tid >> 5] = mx;
    __syncthreads();
    mx = fmaxf(fmaxf(redm[0], redm[1]), fmaxf(redm[2], redm[3]));
    float se = 0.f;
    #pragma unroll
    for (int r = 0; r < 3; r++) { v[r] = expf(v[r] - mx); se += v[r]; }
    #pragma unroll
    for (int o = 16; o; o >>= 1) se += __shfl_xor_sync(0xffffffffu, se, o);
    if ((tid & 31) == 0) reds[tid >> 5] = se;
    __syncthreads();
    se = reds[0] + reds[1] + reds[2] + reds[3];
    float inv = 1.0f / se;
    __half* dst = g_attnh + (size_t)h*LL + (size_t)i*L;
    #pragma unroll
    for (int r = 0; r < 3; r++) dst[tid + r*128] = __float2half(v[r] * inv);
}

// ---------------- kernel 6: AV per-head GEMM, fp16 MMA, trans-B ----------------
__global__ __launch_bounds__(256, 2) void k_o()
{
    extern __shared__ __half smh[];
    __half* As = smh;                    // [2 st][2 c2][128][40]
    __half* Bs = smh + 2*2*128*40;       // [2 st][64][136]
    int i0  = blockIdx.x * 128;
    int nd0 = blockIdx.y * 128;
    int h   = blockIdx.z;
    int tid = threadIdx.x;
    int w = tid >> 5, lane = tid & 31;
    int wm = w >> 1, wn = w & 1;
    int lrow = lane >> 2, lq = lane & 3;
    const __half* A = g_attnh + (size_t)h*LL;
    const __half* B = g_vh + (size_t)h*L*ND;

    unsigned aBase = (unsigned)__cvta_generic_to_shared(As);
    unsigned bBase = (unsigned)__cvta_generic_to_shared(Bs);
    unsigned aLane = (unsigned)((lane & 15)*80 + ((lane >> 4) & 1)*16);
    // trans-B lane mapping: row j = (lane&7) + ((lane>>3)&1)*8 ; col n += ((lane>>4)&1)*8
    unsigned bRow = (unsigned)((lane & 7) + ((lane >> 3) & 1)*8);
    unsigned bCol = (unsigned)(((lane >> 4) & 1)*8);

    auto load = [&](int st, int k0) {    // j-chunk of 64
        #pragma unroll
        for (int it = 0; it < 4; it++) {
            int cid = tid + it*256;
            int c2 = cid >> 9, rem = cid & 511;
            int row = rem >> 2, part = rem & 3;
            cpa16(As + ((st*2 + c2)*128 + row)*40 + part*8,
                  A + (size_t)(i0+row)*L + k0 + c2*32 + part*8);
        }
        #pragma unroll
        for (int it = 0; it < 4; it++) {
            int cid = tid + it*256;      // 1024 chunks: 64 rows x 16 parts
            int row = cid >> 4, part = cid & 15;
            cpa16(Bs + (st*64 + row)*136 + part*8,
                  B + (size_t)(k0+row)*ND + nd0 + part*8);
        }
    };

    float acc[2][8][4];
    #pragma unroll
    for (int mt = 0; mt < 2; mt++)
        #pragma unroll
        for (int nt = 0; nt < 8; nt++)
            #pragma unroll
            for (int r = 0; r < 4; r++) acc[mt][nt][r] = 0.f;

    load(0, 0); CPA_COMMIT;
    for (int it = 0; it < 6; it++) {
        CPA_WAIT0; __syncthreads();
        if (it+1 < 6) { load((it+1)&1, (it+1)*64); CPA_COMMIT; }
        int st = it & 1;
        unsigned bTile = bBase + (unsigned)(st*64*272);
        #pragma unroll
        for (int c2 = 0; c2 < 2; c2++) {
            unsigned aTile = aBase + (unsigned)((st*2 + c2)*128*80);
            #pragma unroll
            for (int ks = 0; ks < 2; ks++) {
                int ks2 = c2*2 + ks;     // j 16-block within 64
                unsigned a[2][4], b[8][2];
                #pragma unroll
                for (int mt = 0; mt < 2; mt++) {
                    unsigned addr = aTile + (unsigned)((wm*32 + mt*16)*80 + ks*32) + aLane;
                    LDSM4(a[mt][0], a[mt][1], a[mt][2], a[mt][3], addr);
                }
                #pragma unroll
                for (int np = 0; np < 4; np++) {
                    unsigned addr = bTile + (ks2*16 + bRow)*272
                                  + (unsigned)(wn*64 + np*16 + bCol)*2;
                    LDSM4T(b[2*np][0], b[2*np][1], b[2*np+1][0], b[2*np+1][1], addr);
                }
                #pragma unroll
                for (int mt = 0; mt < 2; mt++)
                    #pragma unroll
                    for (int nt = 0; nt < 8; nt++)
                        mma16(acc[mt][nt], a[mt], b[nt]);
            }
        }
    }
    #pragma unroll
    for (int mt = 0; mt < 2; mt++)
        #pragma unroll
        for (int hf = 0; hf < 2; hf++) {
            int i = i0 + wm*32 + mt*16 + lrow + hf*8;
            #pragma unroll
            for (int nt = 0; nt < 8; nt++) {
                int nd = nd0 + wn*64 + nt*8 + 2*lq;
                int n = nd >> 5, d = nd & 31;
                size_t off = (size_t)(n*L + i)*DP + h*DH + d;
                float2 gv = __half22float2(*(const __half2*)(g_gateh + off));
                *(__half2*)(g_oh + off) =
                    __floats2half2_rn(acc[mt][nt][hf*2]  * gv.x,
                                      acc[mt][nt][hf*2+1]* gv.y);
            }
        }
}

// ---------------- kernel 7: out = g_oh @ WoutT + bout, fp16 MMA ----------------
__global__ __launch_bounds__(256, 2) void k_out(const float* __restrict__ bout,
                                                float* __restrict__ out)
{
    extern __shared__ __half smh[];
    __half* As = smh;                    // [2 st][128][40]
    __half* Bh = smh + 2*128*40;         // [128][136] resident
    int m0 = blockIdx.x * 128;
    int n  = m0 / L;
    int ib = m0 % L;
    int tid = threadIdx.x;
    int w = tid >> 5, lane = tid & 31;
    int wm = w >> 1, wn = w & 1;
    int lrow = lane >> 2, lq = lane & 3;

    unsigned aBase = (unsigned)__cvta_generic_to_shared(As);
    unsigned bBase = (unsigned)__cvta_generic_to_shared(Bh);
    unsigned aLane = (unsigned)((lane & 15)*80 + ((lane >> 4) & 1)*16);
    unsigned bLane = (unsigned)((((lane >> 4) & 1)*8 + (lane & 7))*272 + ((lane >> 3) & 1)*16);

    auto loadA = [&](int st, int kt) {
        #pragma unroll
        for (int it = 0; it < 2; it++) {
            int cid = tid + it*256;
            int row = cid >> 2, part = cid & 3;
            cpa16(As + (st*128 + row)*40 + part*8,
                  g_oh + (size_t)(m0+row)*DP + kt*32 + part*8);
        }
    };
    #pragma unroll
    for (int it = 0; it < 8; it++) {
        int cid = tid + it*256;
        int row = cid >> 4, part = cid & 15;
        cpa16(Bh + row*136 + part*8, g_woutT + (size_t)row*DP + part*8);
    }
    loadA(0, 0); CPA_COMMIT;

    float acc[2][8][4];
    #pragma unroll
    for (int mt = 0; mt < 2; mt++)
        #pragma unroll
        for (int nt = 0; nt < 8; nt++)
            #pragma unroll
            for (int r = 0; r < 4; r++) acc[mt][nt][r] = 0.f;

    for (int kt = 0; kt < 4; kt++) {
        CPA_WAIT0; __syncthreads();
        if (kt < 3) { loadA((kt+1)&1, kt+1); CPA_COMMIT; }
        int st = kt & 1;
        #pragma unroll
        for (int ks = 0; ks < 2; ks++) {
            unsigned a[2][4], b[8][2];
            #pragma unroll
            for (int mt = 0; mt < 2; mt++) {
                unsigned addr = aBase + (unsigned)(st*128*80 + (wm*32 + mt*16)*80 + ks*32) + aLane;
                LDSM4(a[mt][0], a[mt][1], a[mt][2], a[mt][3], addr);
            }
            #pragma unroll
            for (int np = 0; np < 4; np++) {
                unsigned addr = bBase + (unsigned)((wn*64 + np*16)*272 + kt*64 + ks*32) + bLane;
                LDSM4(b[2*np][0], b[2*np][1], b[2*np+1][0], b[2*np+1][1], addr);
            }
            #pragma unroll
            for (int mt = 0; mt < 2; mt++)
                #pragma unroll
                for (int nt = 0; nt < 8; nt++)
                    mma16(acc[mt][nt], a[mt], b[nt]);
        }
    }
    #pragma unroll
    for (int mt = 0; mt < 2; mt++)
        #pragma unroll
        for (int hf = 0; hf < 2; hf++) {
            int i = ib + wm*32 + mt*16 + lrow + hf*8;
            size_t row = (size_t)i*L + n;
            #pragma unroll
            for (int nt = 0; nt < 8; nt++) {
                int c = wn*64 + nt*8 + 2*lq;
                *(float2*)(out + row*DP + c) =
                    make_float2(acc[mt][nt][hf*2]   + bout[c],
                                acc[mt][nt][hf*2+1] + bout[c+1]);
            }
        }
}

// ---------------- launch ----------------
extern "C" void kernel_launch(void* const* d_in, const int* in_sizes, int n_in,
                              void* d_out, int out_size)
{
    const float* pair    = (const float*)d_in[0];
    const float* bias    = (const float*)d_in[1];
    const float* gamma_p = (const float*)d_in[2];
    const float* beta_p  = (const float*)d_in[3];
    const float* gamma_b = (const float*)d_in[4];
    const float* beta_b  = (const float*)d_in[5];
    const float* Wq      = (const float*)d_in[6];
    const float* Wk      = (const float*)d_in[7];
    const float* Wv      = (const float*)d_in[8];
    const float* Wb      = (const float*)d_in[9];
    const float* Wg      = (const float*)d_in[10];
    const float* bg      = (const float*)d_in[11];
    const float* Wout    = (const float*)d_in[12];
    const float* bout    = (const float*)d_in[13];
    float* out = (float*)d_out;

    const int smProj = 128*136*2 + 2*128*136*2;      // 104448
    const int smQK   = 2 * (2*2*128*40) * 2;         // 81920
    const int smO    = (2*2*128*40 + 2*64*136) * 2;  // 40960 + 34816 = 75776
    const int smOut  = 2*128*40*2 + 128*136*2;       // 55296

    static cudaStream_t s1;
    static cudaEvent_t evFork, evPrep, evJoin;
    static int inited = 0;
    if (!inited) {
        cudaFuncSetAttribute(k_projf, cudaFuncAttributeMaxDynamicSharedMemorySize, smProj);
        cudaFuncSetAttribute(k_qk,    cudaFuncAttributeMaxDynamicSharedMemorySize, smQK);
        cudaFuncSetAttribute(k_o,     cudaFuncAttributeMaxDynamicSharedMemorySize, smO);
        cudaFuncSetAttribute(k_out,   cudaFuncAttributeMaxDynamicSharedMemorySize, smOut);
        cudaStreamCreateWithFlags(&s1, cudaStreamNonBlocking);
        cudaEventCreateWithFlags(&evFork, cudaEventDisableTiming);
        cudaEventCreateWithFlags(&evPrep, cudaEventDisableTiming);
        cudaEventCreateWithFlags(&evJoin, cudaEventDisableTiming);
        inited = 1;
    }

    cudaEventRecord(evFork, 0);
    cudaStreamWaitEvent(s1, evFork, 0);
    k_prep    <<<320, 256, 0, s1>>>(Wq, Wk, Wv, Wg, Wout);
    cudaEventRecord(evPrep, s1);
    k_bias    <<<LL/8, 256, 0, s1>>>(bias, gamma_b, beta_b, Wb);
    cudaEventRecord(evJoin, s1);

    cudaStreamWaitEvent(0, evPrep, 0);
    k_projf   <<<LL/128, 256, smProj>>>(pair, gamma_p, beta_p, bg);
    k_qk      <<<dim3(3, 3, NH*SPLIT), 256, smQK>>>();

    cudaStreamWaitEvent(0, evJoin, 0);
    k_softmax <<<dim3(L, NH), 128>>>();
    k_o       <<<dim3(3, ND/128, NH), 256, smO>>>();
    k_out     <<<LL/128, 256, smOut>>>(bout, out);
}

// round 15
// speedup vs baseline: 1.5379x; 1.5379x over previous
#include <cuda_runtime.h>
#include <cuda_fp16.h>
#include <math.h>

#define L    384
#define DP   128
#define NH   4
#define DH   32
#define LL   (L*L)            // 147456
#define SPLIT 8
#define NSPL  (L/SPLIT)       // 48
#define ND   (L*DH)           // 12288

// ---------------- scratch ----------------
__device__ __align__(16) __half g_qh [NH*LL*DH];     // q fp16: ((h*L+n)*L+i)*32+d
__device__ __align__(16) __half g_kh [NH*LL*DH];     // k fp16: ((h*L+n)*L+j)*32+d
__device__ __align__(16) __half g_vh [NH*(size_t)L*ND]; // v fp16 NATURAL: (h*L+j)*12288 + n*32+d
__device__ __align__(16) __half g_gateh[LL*DP];      // fp16 gate
__device__ __align__(16) __half g_oh [LL*DP];        // gated fp16, row n*L+i
__device__ __align__(16) __half g_attnh[NH*LL];      // softmax probs fp16 [h][i][j]
__device__ __align__(16) __half g_battnh[NH*LL];     // fp16 [h][i][j]
__device__ __align__(16) __half g_qkph[SPLIT*NH*LL]; // fp16 qk partials [s][h][i][j]
__device__ __align__(16) __half g_w4T [4*DP*DP];     // fp16 TRANSPOSED: [which][n][k]
__device__ __align__(16) __half g_woutT[DP*DP];      // fp16 TRANSPOSED: [n][k]

// ---------------- helpers ----------------
__device__ __forceinline__ void cpa16(void* dst, const void* src) {
    unsigned d = (unsigned)__cvta_generic_to_shared(dst);
    asm volatile("cp.async.cg.shared.global [%0], [%1], 16;\n" :: "r"(d), "l"(src));
}
#define CPA_COMMIT asm volatile("cp.async.commit_group;\n" ::: "memory")
#define CPA_WAIT0  asm volatile("cp.async.wait_group 0;\n" ::: "memory")

__device__ __forceinline__ void mma16(float c[4], const unsigned a[4], const unsigned b[2]) {
    asm volatile(
        "mma.sync.aligned.m16n8k16.row.col.f32.f16.f16.f32 "
        "{%0,%1,%2,%3},{%4,%5,%6,%7},{%8,%9},{%0,%1,%2,%3};\n"
        : "+f"(c[0]), "+f"(c[1]), "+f"(c[2]), "+f"(c[3])
        : "r"(a[0]), "r"(a[1]), "r"(a[2]), "r"(a[3]), "r"(b[0]), "r"(b[1]));
}
#define LDSM4(r0,r1,r2,r3,addr) \
    asm volatile("ldmatrix.sync.aligned.m8n8.x4.shared.b16 {%0,%1,%2,%3}, [%4];" \
                 : "=r"(r0), "=r"(r1), "=r"(r2), "=r"(r3) : "r"(addr))
#define LDSM4T(r0,r1,r2,r3,addr) \
    asm volatile("ldmatrix.sync.aligned.m8n8.x4.trans.shared.b16 {%0,%1,%2,%3}, [%4];" \
                 : "=r"(r0), "=r"(r1), "=r"(r2), "=r"(r3) : "r"(addr))

// ---------------- kernel 0: transpose + fp16-convert weights ----------------
__global__ __launch_bounds__(256) void k_prep(const float* __restrict__ Wq,
                                              const float* __restrict__ Wk,
                                              const float* __restrict__ Wv,
                                              const float* __restrict__ Wg,
                                              const float* __restrict__ Wout)
{
    int id = blockIdx.x * 256 + threadIdx.x;     // 81920
    if (id < 4*DP*DP) {
        int which = id >> 14, rem = id & (DP*DP - 1);
        int n = rem >> 7, k = rem & 127;
        const float* W = (which==0) ? Wq : (which==1) ? Wk : (which==2) ? Wv : Wg;
        g_w4T[id] = __float2half(W[k*DP + n]);
    } else {
        int rem = id - 4*DP*DP;
        int n = rem >> 7, k = rem & 127;
        g_woutT[rem] = __float2half(Wout[k*DP + n]);
    }
}

// ---------------- kernel 2: bias path ----------------
__global__ __launch_bounds__(256) void k_bias(const float* __restrict__ bias,
                                              const float* __restrict__ gamma,
                                              const float* __restrict__ beta,
                                              const float* __restrict__ Wb)
{
    int warp = (blockIdx.x * blockDim.x + threadIdx.x) >> 5;
    int lane = threadIdx.x & 31;
    if (warp >= LL) return;
    int j = warp / L, i = warp % L;
    float4 x = ((const float4*)(bias + (size_t)warp * DP))[lane];
    float s  = x.x + x.y + x.z + x.w;
    float ss = x.x*x.x + x.y*x.y + x.z*x.z + x.w*x.w;
    #pragma unroll
    for (int o = 16; o; o >>= 1) {
        s  += __shfl_xor_sync(0xffffffffu, s,  o);
        ss += __shfl_xor_sync(0xffffffffu, ss, o);
    }
    float mean = s * (1.0f/DP);
    float var  = ss * (1.0f/DP) - mean*mean;
    float inv  = rsqrtf(var + 1e-5f);
    float4 g = ((const float4*)gamma)[lane];
    float4 b = ((const float4*)beta )[lane];
    float y[4];
    y[0] = (x.x - mean)*inv*g.x + b.x;
    y[1] = (x.y - mean)*inv*g.y + b.y;
    y[2] = (x.z - mean)*inv*g.z + b.z;
    y[3] = (x.w - mean)*inv*g.w + b.w;
    float acc[NH] = {0.f, 0.f, 0.f, 0.f};
    #pragma unroll
    for (int t = 0; t < 4; t++) {
        int c = lane*4 + t;
        #pragma unroll
        for (int h = 0; h < NH; h++)
            acc[h] += y[t] * Wb[c*NH + h];
    }
    #pragma unroll
    for (int h = 0; h < NH; h++)
        #pragma unroll
        for (int o = 16; o; o >>= 1)
            acc[h] += __shfl_xor_sync(0xffffffffu, acc[h], o);
    if (lane == 0) {
        #pragma unroll
        for (int h = 0; h < NH; h++)
            g_battnh[(size_t)h*LL + (size_t)i*L + j] = __float2half(acc[h]);
    }
}

// ---------------- kernel 3: fused LN + 4 projections, fp16 MMA ----------------
__global__ __launch_bounds__(256, 2) void k_projf(const float* __restrict__ pair,
                                                  const float* __restrict__ gamma,
                                                  const float* __restrict__ beta,
                                                  const float* __restrict__ bg)
{
    extern __shared__ char smraw[];
    __half (*Ah)[136] = (__half(*)[136])smraw;
    char* warea = smraw + 128*136*2;
    float (*Pf)[132]      = (float(*)[132])warea;
    __half (*Wh)[128][136] = (__half(*)[128][136])warea;

    int m0 = blockIdx.x * 128;
    int n  = m0 / L;
    int i0 = m0 % L;
    int tid = threadIdx.x;
    int w = tid >> 5, lane = tid & 31;
    int wm = w >> 1, wn = w & 1;
    int lrow = lane >> 2, lq = lane & 3;

    #pragma unroll
    for (int it = 0; it < 16; it++) {
        int cid = tid + it*256;
        int row = cid >> 5, part = cid & 31;
        cpa16(&Pf[row][part*4], pair + ((size_t)(i0+row)*L + n)*DP + part*4);
    }
    CPA_COMMIT; CPA_WAIT0; __syncthreads();

    {
        float4 gm = ((const float4*)gamma)[lane];
        float4 bt = ((const float4*)beta )[lane];
        #pragma unroll
        for (int r = 0; r < 16; r++) {
            int row = w*16 + r;
            float4 x = *(float4*)&Pf[row][lane*4];
            float s  = x.x + x.y + x.z + x.w;
            float ss = x.x*x.x + x.y*x.y + x.z*x.z + x.w*x.w;
            #pragma unroll
            for (int o = 16; o; o >>= 1) {
                s  += __shfl_xor_sync(0xffffffffu, s,  o);
                ss += __shfl_xor_sync(0xffffffffu, ss, o);
            }
            float mean = s * (1.0f/DP);
            float var  = ss * (1.0f/DP) - mean*mean;
            float inv  = rsqrtf(var + 1e-5f);
            __half2 h01 = __floats2half2_rn((x.x - mean)*inv*gm.x + bt.x,
                                            (x.y - mean)*inv*gm.y + bt.y);
            __half2 h23 = __floats2half2_rn((x.z - mean)*inv*gm.z + bt.z,
                                            (x.w - mean)*inv*gm.w + bt.w);
            *(__half2*)&Ah[row][lane*4]   = h01;
            *(__half2*)&Ah[row][lane*4+2] = h23;
        }
    }
    __syncthreads();

    unsigned aBase = (unsigned)__cvta_generic_to_shared(&Ah[0][0]);
    unsigned aLane = (unsigned)((lane & 15)*272 + ((lane >> 4) & 1)*16);
    unsigned bLane = (unsigned)((((lane >> 4) & 1)*8 + (lane & 7))*272 + ((lane >> 3) & 1)*16);

    auto loadW = [&](int buf, int which) {
        #pragma unroll
        for (int it = 0; it < 8; it++) {
            int cid = tid + it*256;
            int row = cid >> 4, part = cid & 15;
            cpa16(&Wh[buf][row][part*8],
                  g_w4T + (size_t)which*DP*DP + (size_t)row*DP + part*8);
        }
    };
    loadW(0, 0); CPA_COMMIT;

    const float qscale = 0.17677669529663689f;
    const float kscale = 1.0f / (float)L;

    for (int which = 0; which < 4; which++) {
        CPA_WAIT0; __syncthreads();
        if (which < 3) { loadW((which+1)&1, which+1); CPA_COMMIT; }
        int buf = which & 1;
        unsigned wBase = (unsigned)__cvta_generic_to_shared(&Wh[buf][0][0]);

        float acc[2][8][4];
        #pragma unroll
        for (int mt = 0; mt < 2; mt++)
            #pragma unroll
            for (int nt = 0; nt < 8; nt++)
                #pragma unroll
                for (int r = 0; r < 4; r++) acc[mt][nt][r] = 0.f;

        #pragma unroll
        for (int ks = 0; ks < 8; ks++) {
            unsigned a[2][4], b[8][2];
            #pragma unroll
            for (int mt = 0; mt < 2; mt++) {
                unsigned addr = aBase + (unsigned)((wm*32 + mt*16)*272 + ks*32) + aLane;
                LDSM4(a[mt][0], a[mt][1], a[mt][2], a[mt][3], addr);
            }
            #pragma unroll
            for (int np = 0; np < 4; np++) {
                unsigned addr = wBase + (unsigned)((wn*64 + np*16)*272 + ks*32) + bLane;
                LDSM4(b[2*np][0], b[2*np][1], b[2*np+1][0], b[2*np+1][1], addr);
            }
            #pragma unroll
            for (int mt = 0; mt < 2; mt++)
                #pragma unroll
                for (int nt = 0; nt < 8; nt++)
                    mma16(acc[mt][nt], a[mt], b[nt]);
        }

        #pragma unroll
        for (int mt = 0; mt < 2; mt++) {
            #pragma unroll
            for (int hf = 0; hf < 2; hf++) {
                int i = i0 + wm*32 + mt*16 + lrow + hf*8;
                #pragma unroll
                for (int nt = 0; nt < 8; nt++) {
                    int cc = wn*64 + nt*8 + 2*lq;
                    float v0 = acc[mt][nt][hf*2+0];
                    float v1 = acc[mt][nt][hf*2+1];
                    if (which == 0) {
                        int h = cc >> 5, d = cc & 31;
                        *(__half2*)(g_qh + ((size_t)(h*L+n)*L + i)*DH + d) =
                            __floats2half2_rn(v0*qscale, v1*qscale);
                    } else if (which == 1) {
                        int h = cc >> 5, d = cc & 31;
                        *(__half2*)(g_kh + ((size_t)(h*L+n)*L + i)*DH + d) =
                            __floats2half2_rn(v0*kscale, v1*kscale);
                    } else if (which == 2) {
                        int h = cc >> 5, d = cc & 31;   // i is j here
                        *(__half2*)(g_vh + ((size_t)(h*L) + i)*ND + n*DH + d) =
                            __floats2half2_rn(v0, v1);
                    } else {
                        v0 = 1.0f/(1.0f + expf(-(v0 + bg[cc  ])));
                        v1 = 1.0f/(1.0f + expf(-(v1 + bg[cc+1])));
                        *(__half2*)(g_gateh + ((size_t)(n*L+i))*DP + cc) =
                            __floats2half2_rn(v0, v1);
                    }
                }
            }
        }
    }
}

// ---------------- kernel 4: QK logits, fp16 MMA + ldmatrix ----------------
__global__ __launch_bounds__(256, 2) void k_qk()
{
    extern __shared__ __half smh[];
    __half* Qs = smh;                   // [2 st][2 n2][128][40]
    __half* Ks = smh + 2*2*128*40;
    int i0 = blockIdx.x * 128, j0 = blockIdx.y * 128;
    int h = blockIdx.z & 3, s = blockIdx.z >> 2;
    int tid = threadIdx.x;
    int w = tid >> 5, lane = tid & 31;
    int wm = w >> 1, wn = w & 1;
    int lrow = lane >> 2, lq = lane & 3;
    const __half* Qg = g_qh + (size_t)h*L*L*DH;
    const __half* Kg = g_kh + (size_t)h*L*L*DH;

    unsigned qBase = (unsigned)__cvta_generic_to_shared(Qs);
    unsigned kBase = (unsigned)__cvta_generic_to_shared(Ks);
    unsigned aLane = (unsigned)((lane & 15)*80 + ((lane >> 4) & 1)*16);
    unsigned bLane = (unsigned)((((lane >> 4) & 1)*8 + (lane & 7))*80 + ((lane >> 3) & 1)*16);

    auto load = [&](int st, int n) {
        #pragma unroll
        for (int it = 0; it < 4; it++) {
            int cid = tid + it*256;
            int n2 = cid >> 9, rem = cid & 511;
            int row = rem >> 2, part = rem & 3;
            cpa16(Qs + ((st*2 + n2)*128 + row)*40 + part*8,
                  Qg + ((size_t)(n+n2)*L + i0 + row)*DH + part*8);
        }
        #pragma unroll
        for (int it = 0; it < 4; it++) {
            int cid = tid + it*256;
            int n2 = cid >> 9, rem = cid & 511;
            int row = rem >> 2, part = rem & 3;
            cpa16(Ks + ((st*2 + n2)*128 + row)*40 + part*8,
                  Kg + ((size_t)(n+n2)*L + j0 + row)*DH + part*8);
        }
    };

    float acc[2][8][4];
    #pragma unroll
    for (int mt = 0; mt < 2; mt++)
        #pragma unroll
        for (int nt = 0; nt < 8; nt++)
            #pragma unroll
            for (int r = 0; r < 4; r++) acc[mt][nt][r] = 0.f;

    load(0, s*NSPL); CPA_COMMIT;
    const int IT = NSPL/2;
    for (int it = 0; it < IT; it++) {
        CPA_WAIT0; __syncthreads();
        if (it+1 < IT) { load((it+1)&1, s*NSPL + (it+1)*2); CPA_COMMIT; }
        int st = it & 1;
        #pragma unroll
        for (int n2 = 0; n2 < 2; n2++) {
            unsigned qTile = qBase + (unsigned)((st*2 + n2)*128*80);
            unsigned kTile = kBase + (unsigned)((st*2 + n2)*128*80);
            #pragma unroll
            for (int ks = 0; ks < 2; ks++) {
                unsigned a[2][4], b[8][2];
                #pragma unroll
                for (int mt = 0; mt < 2; mt++) {
                    unsigned addr = qTile + (unsigned)((wm*32 + mt*16)*80 + ks*32) + aLane;
                    LDSM4(a[mt][0], a[mt][1], a[mt][2], a[mt][3], addr);
                }
                #pragma unroll
                for (int np = 0; np < 4; np++) {
                    unsigned addr = kTile + (unsigned)((wn*64 + np*16)*80 + ks*32) + bLane;
                    LDSM4(b[2*np][0], b[2*np][1], b[2*np+1][0], b[2*np+1][1], addr);
                }
                #pragma unroll
                for (int mt = 0; mt < 2; mt++)
                    #pragma unroll
                    for (int nt = 0; nt < 8; nt++)
                        mma16(acc[mt][nt], a[mt], b[nt]);
            }
        }
    }
    __half* dst = g_qkph + (size_t)(s*NH + h)*LL;
    #pragma unroll
    for (int mt = 0; mt < 2; mt++)
        #pragma unroll
        for (int hf = 0; hf < 2; hf++) {
            int i = i0 + wm*32 + mt*16 + lrow + hf*8;
            #pragma unroll
            for (int nt = 0; nt < 8; nt++) {
                int j = j0 + wn*64 + nt*8 + 2*lq;
                *(__half2*)(dst + (size_t)i*L + j) =
                    __floats2half2_rn(acc[mt][nt][hf*2], acc[mt][nt][hf*2+1]);
            }
        }
}

// ---------------- kernel 5: softmax -> fp16 probs ----------------
__global__ __launch_bounds__(128) void k_softmax()
{
    __shared__ float redm[4], reds[4];
    int i = blockIdx.x, h = blockIdx.y;
    int tid = threadIdx.x;
    float v[3];
    float mx = -1e30f;
    #pragma unroll
    for (int r = 0; r < 3; r++) {
        int j = tid + r*128;
        float a = __half2float(g_battnh[(size_t)h*LL + (size_t)i*L + j]);
        #pragma unroll
        for (int s = 0; s < SPLIT; s++)
            a += __half2float(g_qkph[(size_t)(s*NH + h)*LL + (size_t)i*L + j]);
        v[r] = a;
        mx = fmaxf(mx, a);
    }
    #pragma unroll
    for (int o = 16; o; o >>= 1) mx = fmaxf(mx, __shfl_xor_sync(0xffffffffu, mx, o));
    if ((tid & 31) == 0) redm[tid >> 5] = mx;
    __syncthreads();
    mx = fmaxf(fmaxf(redm[0], redm[1]), fmaxf(redm[2], redm[3]));
    float se = 0.f;
    #pragma unroll
    for (int r = 0; r < 3; r++) { v[r] = expf(v[r] - mx); se += v[r]; }
    #pragma unroll
    for (int o = 16; o; o >>= 1) se += __shfl_xor_sync(0xffffffffu, se, o);
    if ((tid & 31) == 0) reds[tid >> 5] = se;
    __syncthreads();
    se = reds[0] + reds[1] + reds[2] + reds[3];
    float inv = 1.0f / se;
    __half* dst = g_attnh + (size_t)h*LL + (size_t)i*L;
    #pragma unroll
    for (int r = 0; r < 3; r++) dst[tid + r*128] = __float2half(v[r] * inv);
}

// ---------------- kernel 6: AV per-head GEMM, fp16 MMA, trans-B ----------------
__global__ __launch_bounds__(256, 2) void k_o()
{
    extern __shared__ __half smh[];
    __half* As = smh;                    // [2 st][2 c2][128][40]
    __half* Bs = smh + 2*2*128*40;       // [2 st][64][136]
    int i0  = blockIdx.x * 128;
    int nd0 = blockIdx.y * 128;
    int h   = blockIdx.z;
    int tid = threadIdx.x;
    int w = tid >> 5, lane = tid & 31;
    int wm = w >> 1, wn = w & 1;
    int lrow = lane >> 2, lq = lane & 3;
    const __half* A = g_attnh + (size_t)h*LL;
    const __half* B = g_vh + (size_t)h*L*ND;

    unsigned aBase = (unsigned)__cvta_generic_to_shared(As);
    unsigned bBase = (unsigned)__cvta_generic_to_shared(Bs);
    unsigned aLane = (unsigned)((lane & 15)*80 + ((lane >> 4) & 1)*16);
    unsigned bRow = (unsigned)((lane & 7) + ((lane >> 3) & 1)*8);
    unsigned bCol = (unsigned)(((lane >> 4) & 1)*8);

    auto load = [&](int st, int k0) {
        #pragma unroll
        for (int it = 0; it < 4; it++) {
            int cid = tid + it*256;
            int c2 = cid >> 9, rem = cid & 511;
            int row = rem >> 2, part = rem & 3;
            cpa16(As + ((st*2 + c2)*128 + row)*40 + part*8,
                  A + (size_t)(i0+row)*L + k0 + c2*32 + part*8);
        }
        #pragma unroll
        for (int it = 0; it < 4; it++) {
            int cid = tid + it*256;
            int row = cid >> 4, part = cid & 15;
            cpa16(Bs + (st*64 + row)*136 + part*8,
                  B + (size_t)(k0+row)*ND + nd0 + part*8);
        }
    };

    float acc[2][8][4];
    #pragma unroll
    for (int mt = 0; mt < 2; mt++)
        #pragma unroll
        for (int nt = 0; nt < 8; nt++)
            #pragma unroll
            for (int r = 0; r < 4; r++) acc[mt][nt][r] = 0.f;

    load(0, 0); CPA_COMMIT;
    for (int it = 0; it < 6; it++) {
        CPA_WAIT0; __syncthreads();
        if (it+1 < 6) { load((it+1)&1, (it+1)*64); CPA_COMMIT; }
        int st = it & 1;
        unsigned bTile = bBase + (unsigned)(st*64*272);
        #pragma unroll
        for (int c2 = 0; c2 < 2; c2++) {
            unsigned aTile = aBase + (unsigned)((st*2 + c2)*128*80);
            #pragma unroll
            for (int ks = 0; ks < 2; ks++) {
                int ks2 = c2*2 + ks;
                unsigned a[2][4], b[8][2];
                #pragma unroll
                for (int mt = 0; mt < 2; mt++) {
                    unsigned addr = aTile + (unsigned)((wm*32 + mt*16)*80 + ks*32) + aLane;
                    LDSM4(a[mt][0], a[mt][1], a[mt][2], a[mt][3], addr);
                }
                #pragma unroll
                for (int np = 0; np < 4; np++) {
                    unsigned addr = bTile + (ks2*16 + bRow)*272
                                  + (unsigned)(wn*64 + np*16 + bCol)*2;
                    LDSM4T(b[2*np][0], b[2*np][1], b[2*np+1][0], b[2*np+1][1], addr);
                }
                #pragma unroll
                for (int mt = 0; mt < 2; mt++)
                    #pragma unroll
                    for (int nt = 0; nt < 8; nt++)
                        mma16(acc[mt][nt], a[mt], b[nt]);
            }
        }
    }
    #pragma unroll
    for (int mt = 0; mt < 2; mt++)
        #pragma unroll
        for (int hf = 0; hf < 2; hf++) {
            int i = i0 + wm*32 + mt*16 + lrow + hf*8;
            #pragma unroll
            for (int nt = 0; nt < 8; nt++) {
                int nd = nd0 + wn*64 + nt*8 + 2*lq;
                int n = nd >> 5, d = nd & 31;
                size_t off = (size_t)(n*L + i)*DP + h*DH + d;
                float2 gv = __half22float2(*(const __half2*)(g_gateh + off));
                *(__half2*)(g_oh + off) =
                    __floats2half2_rn(acc[mt][nt][hf*2]  * gv.x,
                                      acc[mt][nt][hf*2+1]* gv.y);
            }
        }
}

// ---------------- kernel 7: out = g_oh @ WoutT + bout, fp16 MMA ----------------
__global__ __launch_bounds__(256, 2) void k_out(const float* __restrict__ bout,
                                                float* __restrict__ out)
{
    extern __shared__ __half smh[];
    __half* As = smh;                    // [2 st][128][40]
    __half* Bh = smh + 2*128*40;         // [128][136] resident
    int m0 = blockIdx.x * 128;
    int n  = m0 / L;
    int ib = m0 % L;
    int tid = threadIdx.x;
    int w = tid >> 5, lane = tid & 31;
    int wm = w >> 1, wn = w & 1;
    int lrow = lane >> 2, lq = lane & 3;

    unsigned aBase = (unsigned)__cvta_generic_to_shared(As);
    unsigned bBase = (unsigned)__cvta_generic_to_shared(Bh);
    unsigned aLane = (unsigned)((lane & 15)*80 + ((lane >> 4) & 1)*16);
    unsigned bLane = (unsigned)((((lane >> 4) & 1)*8 + (lane & 7))*272 + ((lane >> 3) & 1)*16);

    auto loadA = [&](int st, int kt) {
        #pragma unroll
        for (int it = 0; it < 2; it++) {
            int cid = tid + it*256;
            int row = cid >> 2, part = cid & 3;
            cpa16(As + (st*128 + row)*40 + part*8,
                  g_oh + (size_t)(m0+row)*DP + kt*32 + part*8);
        }
    };
    #pragma unroll
    for (int it = 0; it < 8; it++) {
        int cid = tid + it*256;
        int row = cid >> 4, part = cid & 15;
        cpa16(Bh + row*136 + part*8, g_woutT + (size_t)row*DP + part*8);
    }
    loadA(0, 0); CPA_COMMIT;

    float acc[2][8][4];
    #pragma unroll
    for (int mt = 0; mt < 2; mt++)
        #pragma unroll
        for (int nt = 0; nt < 8; nt++)
            #pragma unroll
            for (int r = 0; r < 4; r++) acc[mt][nt][r] = 0.f;

    for (int kt = 0; kt < 4; kt++) {
        CPA_WAIT0; __syncthreads();
        if (kt < 3) { loadA((kt+1)&1, kt+1); CPA_COMMIT; }
        int st = kt & 1;
        #pragma unroll
        for (int ks = 0; ks < 2; ks++) {
            unsigned a[2][4], b[8][2];
            #pragma unroll
            for (int mt = 0; mt < 2; mt++) {
                unsigned addr = aBase + (unsigned)(st*128*80 + (wm*32 + mt*16)*80 + ks*32) + aLane;
                LDSM4(a[mt][0], a[mt][1], a[mt][2], a[mt][3], addr);
            }
            #pragma unroll
            for (int np = 0; np < 4; np++) {
                unsigned addr = bBase + (unsigned)((wn*64 + np*16)*272 + kt*64 + ks*32) + bLane;
                LDSM4(b[2*np][0], b[2*np][1], b[2*np+1][0], b[2*np+1][1], addr);
            }
            #pragma unroll
            for (int mt = 0; mt < 2; mt++)
                #pragma unroll
                for (int nt = 0; nt < 8; nt++)
                    mma16(acc[mt][nt], a[mt], b[nt]);
        }
    }
    #pragma unroll
    for (int mt = 0; mt < 2; mt++)
        #pragma unroll
        for (int hf = 0; hf < 2; hf++) {
            int i = ib + wm*32 + mt*16 + lrow + hf*8;
            size_t row = (size_t)i*L + n;
            #pragma unroll
            for (int nt = 0; nt < 8; nt++) {
                int c = wn*64 + nt*8 + 2*lq;
                *(float2*)(out + row*DP + c) =
                    make_float2(acc[mt][nt][hf*2]   + bout[c],
                                acc[mt][nt][hf*2+1] + bout[c+1]);
            }
        }
}

// ---------------- launch ----------------
extern "C" void kernel_launch(void* const* d_in, const int* in_sizes, int n_in,
                              void* d_out, int out_size)
{
    const float* pair    = (const float*)d_in[0];
    const float* bias    = (const float*)d_in[1];
    const float* gamma_p = (const float*)d_in[2];
    const float* beta_p  = (const float*)d_in[3];
    const float* gamma_b = (const float*)d_in[4];
    const float* beta_b  = (const float*)d_in[5];
    const float* Wq      = (const float*)d_in[6];
    const float* Wk      = (const float*)d_in[7];
    const float* Wv      = (const float*)d_in[8];
    const float* Wb      = (const float*)d_in[9];
    const float* Wg      = (const float*)d_in[10];
    const float* bg      = (const float*)d_in[11];
    const float* Wout    = (const float*)d_in[12];
    const float* bout    = (const float*)d_in[13];
    float* out = (float*)d_out;

    const int smProj = 128*136*2 + 2*128*136*2;      // 104448
    const int smQK   = 2 * (2*2*128*40) * 2;         // 81920
    const int smO    = (2*2*128*40 + 2*64*136) * 2;  // 75776
    const int smOut  = 2*128*40*2 + 128*136*2;       // 55296

    static cudaStream_t s1;
    static cudaEvent_t evFork, evPrep, evJoin;
    static int inited = 0;
    if (!inited) {
        cudaFuncSetAttribute(k_projf, cudaFuncAttributeMaxDynamicSharedMemorySize, smProj);
        cudaFuncSetAttribute(k_qk,    cudaFuncAttributeMaxDynamicSharedMemorySize, smQK);
        cudaFuncSetAttribute(k_o,     cudaFuncAttributeMaxDynamicSharedMemorySize, smO);
        cudaFuncSetAttribute(k_out,   cudaFuncAttributeMaxDynamicSharedMemorySize, smOut);
        cudaStreamCreateWithFlags(&s1, cudaStreamNonBlocking);
        cudaEventCreateWithFlags(&evFork, cudaEventDisableTiming);
        cudaEventCreateWithFlags(&evPrep, cudaEventDisableTiming);
        cudaEventCreateWithFlags(&evJoin, cudaEventDisableTiming);
        inited = 1;
    }

    cudaEventRecord(evFork, 0);
    cudaStreamWaitEvent(s1, evFork, 0);
    k_prep    <<<320, 256, 0, s1>>>(Wq, Wk, Wv, Wg, Wout);
    cudaEventRecord(evPrep, s1);
    k_bias    <<<LL/8, 256, 0, s1>>>(bias, gamma_b, beta_b, Wb);
    cudaEventRecord(evJoin, s1);

    cudaStreamWaitEvent(0, evPrep, 0);
    k_projf   <<<LL/128, 256, smProj>>>(pair, gamma_p, beta_p, bg);
    k_qk      <<<dim3(3, 3, NH*SPLIT), 256, smQK>>>();

    cudaStreamWaitEvent(0, evJoin, 0);
    k_softmax <<<dim3(L, NH), 128>>>();
    k_o       <<<dim3(3, ND/128, NH), 256, smO>>>();
    k_out     <<<LL/128, 256, smOut>>>(bout, out);
}

// round 16
// speedup vs baseline: 1.5609x; 1.0150x over previous
#include <cuda_runtime.h>
#include <cuda_fp16.h>
#include <math.h>

#define L    384
#define DP   128
#define NH   4
#define DH   32
#define LL   (L*L)            // 147456
#define SPLIT 8
#define NSPL  (L/SPLIT)       // 48
#define ND   (L*DH)           // 12288

// ---------------- scratch ----------------
__device__ __align__(16) __half g_pnh[LL*DP];        // LN'd pair_t fp16, row n*L+i
__device__ __align__(16) __half g_qh [NH*LL*DH];     // q fp16: ((h*L+n)*L+i)*32+d
__device__ __align__(16) __half g_kh [NH*LL*DH];     // k fp16: ((h*L+n)*L+j)*32+d
__device__ __align__(16) __half g_vh [NH*(size_t)L*ND]; // v fp16 NATURAL: (h*L+j)*12288 + n*32+d
__device__ __align__(16) __half g_gateh[LL*DP];      // fp16 gate
__device__ __align__(16) __half g_oh [LL*DP];        // gated fp16, row n*L+i
__device__ __align__(16) __half g_attnh[NH*LL];      // softmax probs fp16 [h][i][j]
__device__ __align__(16) __half g_battnh[NH*LL];     // fp16 [h][i][j]
__device__ __align__(16) __half g_qkph[SPLIT*NH*LL]; // fp16 qk partials [s][h][i][j]
__device__ __align__(16) __half g_w4T [4*DP*DP];     // fp16 TRANSPOSED: [which][n][k]
__device__ __align__(16) __half g_woutT[DP*DP];      // fp16 TRANSPOSED: [n][k]

// ---------------- helpers ----------------
__device__ __forceinline__ void cpa16(void* dst, const void* src) {
    unsigned d = (unsigned)__cvta_generic_to_shared(dst);
    asm volatile("cp.async.cg.shared.global [%0], [%1], 16;\n" :: "r"(d), "l"(src));
}
#define CPA_COMMIT asm volatile("cp.async.commit_group;\n" ::: "memory")
#define CPA_WAIT0  asm volatile("cp.async.wait_group 0;\n" ::: "memory")

__device__ __forceinline__ void mma16(float c[4], const unsigned a[4], const unsigned b[2]) {
    asm volatile(
        "mma.sync.aligned.m16n8k16.row.col.f32.f16.f16.f32 "
        "{%0,%1,%2,%3},{%4,%5,%6,%7},{%8,%9},{%0,%1,%2,%3};\n"
        : "+f"(c[0]), "+f"(c[1]), "+f"(c[2]), "+f"(c[3])
        : "r"(a[0]), "r"(a[1]), "r"(a[2]), "r"(a[3]), "r"(b[0]), "r"(b[1]));
}
#define LDSM4(r0,r1,r2,r3,addr) \
    asm volatile("ldmatrix.sync.aligned.m8n8.x4.shared.b16 {%0,%1,%2,%3}, [%4];" \
                 : "=r"(r0), "=r"(r1), "=r"(r2), "=r"(r3) : "r"(addr))
#define LDSM4T(r0,r1,r2,r3,addr) \
    asm volatile("ldmatrix.sync.aligned.m8n8.x4.trans.shared.b16 {%0,%1,%2,%3}, [%4];" \
                 : "=r"(r0), "=r"(r1), "=r"(r2), "=r"(r3) : "r"(addr))

// ---------------- kernel 0: transpose + fp16-convert weights ----------------
__global__ __launch_bounds__(256) void k_prep(const float* __restrict__ Wq,
                                              const float* __restrict__ Wk,
                                              const float* __restrict__ Wv,
                                              const float* __restrict__ Wg,
                                              const float* __restrict__ Wout)
{
    int id = blockIdx.x * 256 + threadIdx.x;     // 81920
    if (id < 4*DP*DP) {
        int which = id >> 14, rem = id & (DP*DP - 1);
        int n = rem >> 7, k = rem & 127;
        const float* W = (which==0) ? Wq : (which==1) ? Wk : (which==2) ? Wv : Wg;
        g_w4T[id] = __float2half(W[k*DP + n]);
    } else {
        int rem = id - 4*DP*DP;
        int n = rem >> 7, k = rem & 127;
        g_woutT[rem] = __float2half(Wout[k*DP + n]);
    }
}

// ---------------- kernel 2: bias path ----------------
__global__ __launch_bounds__(256) void k_bias(const float* __restrict__ bias,
                                              const float* __restrict__ gamma,
                                              const float* __restrict__ beta,
                                              const float* __restrict__ Wb)
{
    int warp = (blockIdx.x * blockDim.x + threadIdx.x) >> 5;
    int lane = threadIdx.x & 31;
    if (warp >= LL) return;
    int j = warp / L, i = warp % L;
    float4 x = ((const float4*)(bias + (size_t)warp * DP))[lane];
    float s  = x.x + x.y + x.z + x.w;
    float ss = x.x*x.x + x.y*x.y + x.z*x.z + x.w*x.w;
    #pragma unroll
    for (int o = 16; o; o >>= 1) {
        s  += __shfl_xor_sync(0xffffffffu, s,  o);
        ss += __shfl_xor_sync(0xffffffffu, ss, o);
    }
    float mean = s * (1.0f/DP);
    float var  = ss * (1.0f/DP) - mean*mean;
    float inv  = rsqrtf(var + 1e-5f);
    float4 g = ((const float4*)gamma)[lane];
    float4 b = ((const float4*)beta )[lane];
    float y[4];
    y[0] = (x.x - mean)*inv*g.x + b.x;
    y[1] = (x.y - mean)*inv*g.y + b.y;
    y[2] = (x.z - mean)*inv*g.z + b.z;
    y[3] = (x.w - mean)*inv*g.w + b.w;
    float acc[NH] = {0.f, 0.f, 0.f, 0.f};
    #pragma unroll
    for (int t = 0; t < 4; t++) {
        int c = lane*4 + t;
        #pragma unroll
        for (int h = 0; h < NH; h++)
            acc[h] += y[t] * Wb[c*NH + h];
    }
    #pragma unroll
    for (int h = 0; h < NH; h++)
        #pragma unroll
        for (int o = 16; o; o >>= 1)
            acc[h] += __shfl_xor_sync(0xffffffffu, acc[h], o);
    if (lane == 0) {
        #pragma unroll
        for (int h = 0; h < NH; h++)
            g_battnh[(size_t)h*LL + (size_t)i*L + j] = __float2half(acc[h]);
    }
}

// ---------------- kernel 3a: LN + Q,K projections (stores LN'd tile) ----------------
__global__ __launch_bounds__(256, 2) void k_projQK(const float* __restrict__ pair,
                                                   const float* __restrict__ gamma,
                                                   const float* __restrict__ beta)
{
    extern __shared__ char smraw[];
    __half (*Ah)[136] = (__half(*)[136])smraw;
    char* warea = smraw + 128*136*2;
    float (*Pf)[132]      = (float(*)[132])warea;
    __half (*Wh)[128][136] = (__half(*)[128][136])warea;

    int m0 = blockIdx.x * 128;
    int n  = m0 / L;
    int i0 = m0 % L;
    int tid = threadIdx.x;
    int w = tid >> 5, lane = tid & 31;
    int wm = w >> 1, wn = w & 1;
    int lrow = lane >> 2, lq = lane & 3;

    #pragma unroll
    for (int it = 0; it < 16; it++) {
        int cid = tid + it*256;
        int row = cid >> 5, part = cid & 31;
        cpa16(&Pf[row][part*4], pair + ((size_t)(i0+row)*L + n)*DP + part*4);
    }
    CPA_COMMIT; CPA_WAIT0; __syncthreads();

    {
        float4 gm = ((const float4*)gamma)[lane];
        float4 bt = ((const float4*)beta )[lane];
        #pragma unroll
        for (int r = 0; r < 16; r++) {
            int row = w*16 + r;
            float4 x = *(float4*)&Pf[row][lane*4];
            float s  = x.x + x.y + x.z + x.w;
            float ss = x.x*x.x + x.y*x.y + x.z*x.z + x.w*x.w;
            #pragma unroll
            for (int o = 16; o; o >>= 1) {
                s  += __shfl_xor_sync(0xffffffffu, s,  o);
                ss += __shfl_xor_sync(0xffffffffu, ss, o);
            }
            float mean = s * (1.0f/DP);
            float var  = ss * (1.0f/DP) - mean*mean;
            float inv  = rsqrtf(var + 1e-5f);
            __half2 h01 = __floats2half2_rn((x.x - mean)*inv*gm.x + bt.x,
                                            (x.y - mean)*inv*gm.y + bt.y);
            __half2 h23 = __floats2half2_rn((x.z - mean)*inv*gm.z + bt.z,
                                            (x.w - mean)*inv*gm.w + bt.w);
            *(__half2*)&Ah[row][lane*4]   = h01;
            *(__half2*)&Ah[row][lane*4+2] = h23;
        }
    }
    __syncthreads();

    // persist LN'd tile for the V/gate kernel (bit-exact reuse)
    #pragma unroll
    for (int it = 0; it < 8; it++) {
        int cid = tid + it*256;              // 2048 16B chunks
        int row = cid >> 4, part = cid & 15;
        *(float4*)(g_pnh + (size_t)(m0+row)*DP + part*8) = *(float4*)&Ah[row][part*8];
    }

    unsigned aBase = (unsigned)__cvta_generic_to_shared(&Ah[0][0]);
    unsigned aLane = (unsigned)((lane & 15)*272 + ((lane >> 4) & 1)*16);
    unsigned bLane = (unsigned)((((lane >> 4) & 1)*8 + (lane & 7))*272 + ((lane >> 3) & 1)*16);

    auto loadW = [&](int buf, int which) {
        #pragma unroll
        for (int it = 0; it < 8; it++) {
            int cid = tid + it*256;
            int row = cid >> 4, part = cid & 15;
            cpa16(&Wh[buf][row][part*8],
                  g_w4T + (size_t)which*DP*DP + (size_t)row*DP + part*8);
        }
    };
    loadW(0, 0); CPA_COMMIT;

    const float qscale = 0.17677669529663689f;
    const float kscale = 1.0f / (float)L;

    for (int which = 0; which < 2; which++) {
        CPA_WAIT0; __syncthreads();
        if (which < 1) { loadW(1, 1); CPA_COMMIT; }
        int buf = which & 1;
        unsigned wBase = (unsigned)__cvta_generic_to_shared(&Wh[buf][0][0]);

        float acc[2][8][4];
        #pragma unroll
        for (int mt = 0; mt < 2; mt++)
            #pragma unroll
            for (int nt = 0; nt < 8; nt++)
                #pragma unroll
                for (int r = 0; r < 4; r++) acc[mt][nt][r] = 0.f;

        #pragma unroll
        for (int ks = 0; ks < 8; ks++) {
            unsigned a[2][4], b[8][2];
            #pragma unroll
            for (int mt = 0; mt < 2; mt++) {
                unsigned addr = aBase + (unsigned)((wm*32 + mt*16)*272 + ks*32) + aLane;
                LDSM4(a[mt][0], a[mt][1], a[mt][2], a[mt][3], addr);
            }
            #pragma unroll
            for (int np = 0; np < 4; np++) {
                unsigned addr = wBase + (unsigned)((wn*64 + np*16)*272 + ks*32) + bLane;
                LDSM4(b[2*np][0], b[2*np][1], b[2*np+1][0], b[2*np+1][1], addr);
            }
            #pragma unroll
            for (int mt = 0; mt < 2; mt++)
                #pragma unroll
                for (int nt = 0; nt < 8; nt++)
                    mma16(acc[mt][nt], a[mt], b[nt]);
        }

        #pragma unroll
        for (int mt = 0; mt < 2; mt++) {
            #pragma unroll
            for (int hf = 0; hf < 2; hf++) {
                int i = i0 + wm*32 + mt*16 + lrow + hf*8;
                #pragma unroll
                for (int nt = 0; nt < 8; nt++) {
                    int cc = wn*64 + nt*8 + 2*lq;
                    float v0 = acc[mt][nt][hf*2+0];
                    float v1 = acc[mt][nt][hf*2+1];
                    int h = cc >> 5, d = cc & 31;
                    if (which == 0) {
                        *(__half2*)(g_qh + ((size_t)(h*L+n)*L + i)*DH + d) =
                            __floats2half2_rn(v0*qscale, v1*qscale);
                    } else {
                        *(__half2*)(g_kh + ((size_t)(h*L+n)*L + i)*DH + d) =
                            __floats2half2_rn(v0*kscale, v1*kscale);
                    }
                }
            }
        }
    }
}

// ---------------- kernel 3b: V + gate projections from stored LN tile ----------------
__global__ __launch_bounds__(256, 2) void k_projVG(const float* __restrict__ bg)
{
    extern __shared__ char smraw[];
    __half (*Ah)[136] = (__half(*)[136])smraw;
    __half (*Wh)[128][136] = (__half(*)[128][136])(smraw + 128*136*2);

    int m0 = blockIdx.x * 128;
    int n  = m0 / L;
    int i0 = m0 % L;
    int tid = threadIdx.x;
    int w = tid >> 5, lane = tid & 31;
    int wm = w >> 1, wn = w & 1;
    int lrow = lane >> 2, lq = lane & 3;

    // load LN'd fp16 tile + Wv concurrently
    #pragma unroll
    for (int it = 0; it < 8; it++) {
        int cid = tid + it*256;              // 2048 chunks
        int row = cid >> 4, part = cid & 15;
        cpa16(&Ah[row][part*8], g_pnh + (size_t)(m0+row)*DP + part*8);
    }
    #pragma unroll
    for (int it = 0; it < 8; it++) {
        int cid = tid + it*256;
        int row = cid >> 4, part = cid & 15;
        cpa16(&Wh[0][row][part*8], g_w4T + (size_t)2*DP*DP + (size_t)row*DP + part*8);
    }
    CPA_COMMIT;
    // prefetch Wg
    #pragma unroll
    for (int it = 0; it < 8; it++) {
        int cid = tid + it*256;
        int row = cid >> 4, part = cid & 15;
        cpa16(&Wh[1][row][part*8], g_w4T + (size_t)3*DP*DP + (size_t)row*DP + part*8);
    }
    CPA_COMMIT;

    unsigned aBase = (unsigned)__cvta_generic_to_shared(&Ah[0][0]);
    unsigned aLane = (unsigned)((lane & 15)*272 + ((lane >> 4) & 1)*16);
    unsigned bLane = (unsigned)((((lane >> 4) & 1)*8 + (lane & 7))*272 + ((lane >> 3) & 1)*16);

    for (int which = 2; which < 4; which++) {
        if (which == 2) { asm volatile("cp.async.wait_group 1;\n" ::: "memory"); }
        else           { CPA_WAIT0; }
        __syncthreads();
        int buf = which - 2;
        unsigned wBase = (unsigned)__cvta_generic_to_shared(&Wh[buf][0][0]);

        float acc[2][8][4];
        #pragma unroll
        for (int mt = 0; mt < 2; mt++)
            #pragma unroll
            for (int nt = 0; nt < 8; nt++)
                #pragma unroll
                for (int r = 0; r < 4; r++) acc[mt][nt][r] = 0.f;

        #pragma unroll
        for (int ks = 0; ks < 8; ks++) {
            unsigned a[2][4], b[8][2];
            #pragma unroll
            for (int mt = 0; mt < 2; mt++) {
                unsigned addr = aBase + (unsigned)((wm*32 + mt*16)*272 + ks*32) + aLane;
                LDSM4(a[mt][0], a[mt][1], a[mt][2], a[mt][3], addr);
            }
            #pragma unroll
            for (int np = 0; np < 4; np++) {
                unsigned addr = wBase + (unsigned)((wn*64 + np*16)*272 + ks*32) + bLane;
                LDSM4(b[2*np][0], b[2*np][1], b[2*np+1][0], b[2*np+1][1], addr);
            }
            #pragma unroll
            for (int mt = 0; mt < 2; mt++)
                #pragma unroll
                for (int nt = 0; nt < 8; nt++)
                    mma16(acc[mt][nt], a[mt], b[nt]);
        }

        #pragma unroll
        for (int mt = 0; mt < 2; mt++) {
            #pragma unroll
            for (int hf = 0; hf < 2; hf++) {
                int i = i0 + wm*32 + mt*16 + lrow + hf*8;
                #pragma unroll
                for (int nt = 0; nt < 8; nt++) {
                    int cc = wn*64 + nt*8 + 2*lq;
                    float v0 = acc[mt][nt][hf*2+0];
                    float v1 = acc[mt][nt][hf*2+1];
                    if (which == 2) {
                        int h = cc >> 5, d = cc & 31;   // i is j here
                        *(__half2*)(g_vh + ((size_t)(h*L) + i)*ND + n*DH + d) =
                            __floats2half2_rn(v0, v1);
                    } else {
                        v0 = 1.0f/(1.0f + expf(-(v0 + bg[cc  ])));
                        v1 = 1.0f/(1.0f + expf(-(v1 + bg[cc+1])));
                        *(__half2*)(g_gateh + ((size_t)(n*L+i))*DP + cc) =
                            __floats2half2_rn(v0, v1);
                    }
                }
            }
        }
    }
}

// ---------------- kernel 4: QK logits, fp16 MMA + ldmatrix ----------------
__global__ __launch_bounds__(256, 2) void k_qk()
{
    extern __shared__ __half smh[];
    __half* Qs = smh;                   // [2 st][2 n2][128][40]
    __half* Ks = smh + 2*2*128*40;
    int i0 = blockIdx.x * 128, j0 = blockIdx.y * 128;
    int h = blockIdx.z & 3, s = blockIdx.z >> 2;
    int tid = threadIdx.x;
    int w = tid >> 5, lane = tid & 31;
    int wm = w >> 1, wn = w & 1;
    int lrow = lane >> 2, lq = lane & 3;
    const __half* Qg = g_qh + (size_t)h*L*L*DH;
    const __half* Kg = g_kh + (size_t)h*L*L*DH;

    unsigned qBase = (unsigned)__cvta_generic_to_shared(Qs);
    unsigned kBase = (unsigned)__cvta_generic_to_shared(Ks);
    unsigned aLane = (unsigned)((lane & 15)*80 + ((lane >> 4) & 1)*16);
    unsigned bLane = (unsigned)((((lane >> 4) & 1)*8 + (lane & 7))*80 + ((lane >> 3) & 1)*16);

    auto load = [&](int st, int n) {
        #pragma unroll
        for (int it = 0; it < 4; it++) {
            int cid = tid + it*256;
            int n2 = cid >> 9, rem = cid & 511;
            int row = rem >> 2, part = rem & 3;
            cpa16(Qs + ((st*2 + n2)*128 + row)*40 + part*8,
                  Qg + ((size_t)(n+n2)*L + i0 + row)*DH + part*8);
        }
        #pragma unroll
        for (int it = 0; it < 4; it++) {
            int cid = tid + it*256;
            int n2 = cid >> 9, rem = cid & 511;
            int row = rem >> 2, part = rem & 3;
            cpa16(Ks + ((st*2 + n2)*128 + row)*40 + part*8,
                  Kg + ((size_t)(n+n2)*L + j0 + row)*DH + part*8);
        }
    };

    float acc[2][8][4];
    #pragma unroll
    for (int mt = 0; mt < 2; mt++)
        #pragma unroll
        for (int nt = 0; nt < 8; nt++)
            #pragma unroll
            for (int r = 0; r < 4; r++) acc[mt][nt][r] = 0.f;

    load(0, s*NSPL); CPA_COMMIT;
    const int IT = NSPL/2;
    for (int it = 0; it < IT; it++) {
        CPA_WAIT0; __syncthreads();
        if (it+1 < IT) { load((it+1)&1, s*NSPL + (it+1)*2); CPA_COMMIT; }
        int st = it & 1;
        #pragma unroll
        for (int n2 = 0; n2 < 2; n2++) {
            unsigned qTile = qBase + (unsigned)((st*2 + n2)*128*80);
            unsigned kTile = kBase + (unsigned)((st*2 + n2)*128*80);
            #pragma unroll
            for (int ks = 0; ks < 2; ks++) {
                unsigned a[2][4], b[8][2];
                #pragma unroll
                for (int mt = 0; mt < 2; mt++) {
                    unsigned addr = qTile + (unsigned)((wm*32 + mt*16)*80 + ks*32) + aLane;
                    LDSM4(a[mt][0], a[mt][1], a[mt][2], a[mt][3], addr);
                }
                #pragma unroll
                for (int np = 0; np < 4; np++) {
                    unsigned addr = kTile + (unsigned)((wn*64 + np*16)*80 + ks*32) + bLane;
                    LDSM4(b[2*np][0], b[2*np][1], b[2*np+1][0], b[2*np+1][1], addr);
                }
                #pragma unroll
                for (int mt = 0; mt < 2; mt++)
                    #pragma unroll
                    for (int nt = 0; nt < 8; nt++)
                        mma16(acc[mt][nt], a[mt], b[nt]);
            }
        }
    }
    __half* dst = g_qkph + (size_t)(s*NH + h)*LL;
    #pragma unroll
    for (int mt = 0; mt < 2; mt++)
        #pragma unroll
        for (int hf = 0; hf < 2; hf++) {
            int i = i0 + wm*32 + mt*16 + lrow + hf*8;
            #pragma unroll
            for (int nt = 0; nt < 8; nt++) {
                int j = j0 + wn*64 + nt*8 + 2*lq;
                *(__half2*)(dst + (size_t)i*L + j) =
                    __floats2half2_rn(acc[mt][nt][hf*2], acc[mt][nt][hf*2+1]);
            }
        }
}

// ---------------- kernel 5: softmax -> fp16 probs ----------------
__global__ __launch_bounds__(128) void k_softmax()
{
    __shared__ float redm[4], reds[4];
    int i = blockIdx.x, h = blockIdx.y;
    int tid = threadIdx.x;
    float v[3];
    float mx = -1e30f;
    #pragma unroll
    for (int r = 0; r < 3; r++) {
        int j = tid + r*128;
        float a = __half2float(g_battnh[(size_t)h*LL + (size_t)i*L + j]);
        #pragma unroll
        for (int s = 0; s < SPLIT; s++)
            a += __half2float(g_qkph[(size_t)(s*NH + h)*LL + (size_t)i*L + j]);
        v[r] = a;
        mx = fmaxf(mx, a);
    }
    #pragma unroll
    for (int o = 16; o; o >>= 1) mx = fmaxf(mx, __shfl_xor_sync(0xffffffffu, mx, o));
    if ((tid & 31) == 0) redm[tid >> 5] = mx;
    __syncthreads();
    mx = fmaxf(fmaxf(redm[0], redm[1]), fmaxf(redm[2], redm[3]));
    float se = 0.f;
    #pragma unroll
    for (int r = 0; r < 3; r++) { v[r] = expf(v[r] - mx); se += v[r]; }
    #pragma unroll
    for (int o = 16; o; o >>= 1) se += __shfl_xor_sync(0xffffffffu, se, o);
    if ((tid & 31) == 0) reds[tid >> 5] = se;
    __syncthreads();
    se = reds[0] + reds[1] + reds[2] + reds[3];
    float inv = 1.0f / se;
    __half* dst = g_attnh + (size_t)h*LL + (size_t)i*L;
    #pragma unroll
    for (int r = 0; r < 3; r++) dst[tid + r*128] = __float2half(v[r] * inv);
}

// ---------------- kernel 6: AV per-head GEMM, fp16 MMA, trans-B ----------------
__global__ __launch_bounds__(256, 2) void k_o()
{
    extern __shared__ __half smh[];
    __half* As = smh;                    // [2 st][2 c2][128][40]
    __half* Bs = smh + 2*2*128*40;       // [2 st][64][136]
    int i0  = blockIdx.x * 128;
    int nd0 = blockIdx.y * 128;
    int h   = blockIdx.z;
    int tid = threadIdx.x;
    int w = tid >> 5, lane = tid & 31;
    int wm = w >> 1, wn = w & 1;
    int lrow = lane >> 2, lq = lane & 3;
    const __half* A = g_attnh + (size_t)h*LL;
    const __half* B = g_vh + (size_t)h*L*ND;

    unsigned aBase = (unsigned)__cvta_generic_to_shared(As);
    unsigned bBase = (unsigned)__cvta_generic_to_shared(Bs);
    unsigned aLane = (unsigned)((lane & 15)*80 + ((lane >> 4) & 1)*16);
    unsigned bRow = (unsigned)((lane & 7) + ((lane >> 3) & 1)*8);
    unsigned bCol = (unsigned)(((lane >> 4) & 1)*8);

    auto load = [&](int st, int k0) {
        #pragma unroll
        for (int it = 0; it < 4; it++) {
            int cid = tid + it*256;
            int c2 = cid >> 9, rem = cid & 511;
            int row = rem >> 2, part = rem & 3;
            cpa16(As + ((st*2 + c2)*128 + row)*40 + part*8,
                  A + (size_t)(i0+row)*L + k0 + c2*32 + part*8);
        }
        #pragma unroll
        for (int it = 0; it < 4; it++) {
            int cid = tid + it*256;
            int row = cid >> 4, part = cid & 15;
            cpa16(Bs + (st*64 + row)*136 + part*8,
                  B + (size_t)(k0+row)*ND + nd0 + part*8);
        }
    };

    float acc[2][8][4];
    #pragma unroll
    for (int mt = 0; mt < 2; mt++)
        #pragma unroll
        for (int nt = 0; nt < 8; nt++)
            #pragma unroll
            for (int r = 0; r < 4; r++) acc[mt][nt][r] = 0.f;

    load(0, 0); CPA_COMMIT;
    for (int it = 0; it < 6; it++) {
        CPA_WAIT0; __syncthreads();
        if (it+1 < 6) { load((it+1)&1, (it+1)*64); CPA_COMMIT; }
        int st = it & 1;
        unsigned bTile = bBase + (unsigned)(st*64*272);
        #pragma unroll
        for (int c2 = 0; c2 < 2; c2++) {
            unsigned aTile = aBase + (unsigned)((st*2 + c2)*128*80);
            #pragma unroll
            for (int ks = 0; ks < 2; ks++) {
                int ks2 = c2*2 + ks;
                unsigned a[2][4], b[8][2];
                #pragma unroll
                for (int mt = 0; mt < 2; mt++) {
                    unsigned addr = aTile + (unsigned)((wm*32 + mt*16)*80 + ks*32) + aLane;
                    LDSM4(a[mt][0], a[mt][1], a[mt][2], a[mt][3], addr);
                }
                #pragma unroll
                for (int np = 0; np < 4; np++) {
                    unsigned addr = bTile + (ks2*16 + bRow)*272
                                  + (unsigned)(wn*64 + np*16 + bCol)*2;
                    LDSM4T(b[2*np][0], b[2*np][1], b[2*np+1][0], b[2*np+1][1], addr);
                }
                #pragma unroll
                for (int mt = 0; mt < 2; mt++)
                    #pragma unroll
                    for (int nt = 0; nt < 8; nt++)
                        mma16(acc[mt][nt], a[mt], b[nt]);
            }
        }
    }
    #pragma unroll
    for (int mt = 0; mt < 2; mt++)
        #pragma unroll
        for (int hf = 0; hf < 2; hf++) {
            int i = i0 + wm*32 + mt*16 + lrow + hf*8;
            #pragma unroll
            for (int nt = 0; nt < 8; nt++) {
                int nd = nd0 + wn*64 + nt*8 + 2*lq;
                int n = nd >> 5, d = nd & 31;
                size_t off = (size_t)(n*L + i)*DP + h*DH + d;
                float2 gv = __half22float2(*(const __half2*)(g_gateh + off));
                *(__half2*)(g_oh + off) =
                    __floats2half2_rn(acc[mt][nt][hf*2]  * gv.x,
                                      acc[mt][nt][hf*2+1]* gv.y);
            }
        }
}

// ---------------- kernel 7: out = g_oh @ WoutT + bout, fp16 MMA ----------------
__global__ __launch_bounds__(256, 2) void k_out(const float* __restrict__ bout,
                                                float* __restrict__ out)
{
    extern __shared__ __half smh[];
    __half* As = smh;                    // [2 st][128][40]
    __half* Bh = smh + 2*128*40;         // [128][136] resident
    int m0 = blockIdx.x * 128;
    int n  = m0 / L;
    int ib = m0 % L;
    int tid = threadIdx.x;
    int w = tid >> 5, lane = tid & 31;
    int wm = w >> 1, wn = w & 1;
    int lrow = lane >> 2, lq = lane & 3;

    unsigned aBase = (unsigned)__cvta_generic_to_shared(As);
    unsigned bBase = (unsigned)__cvta_generic_to_shared(Bh);
    unsigned aLane = (unsigned)((lane & 15)*80 + ((lane >> 4) & 1)*16);
    unsigned bLane = (unsigned)((((lane >> 4) & 1)*8 + (lane & 7))*272 + ((lane >> 3) & 1)*16);

    auto loadA = [&](int st, int kt) {
        #pragma unroll
        for (int it = 0; it < 2; it++) {
            int cid = tid + it*256;
            int row = cid >> 2, part = cid & 3;
            cpa16(As + (st*128 + row)*40 + part*8,
                  g_oh + (size_t)(m0+row)*DP + kt*32 + part*8);
        }
    };
    #pragma unroll
    for (int it = 0; it < 8; it++) {
        int cid = tid + it*256;
        int row = cid >> 4, part = cid & 15;
        cpa16(Bh + row*136 + part*8, g_woutT + (size_t)row*DP + part*8);
    }
    loadA(0, 0); CPA_COMMIT;

    float acc[2][8][4];
    #pragma unroll
    for (int mt = 0; mt < 2; mt++)
        #pragma unroll
        for (int nt = 0; nt < 8; nt++)
            #pragma unroll
            for (int r = 0; r < 4; r++) acc[mt][nt][r] = 0.f;

    for (int kt = 0; kt < 4; kt++) {
        CPA_WAIT0; __syncthreads();
        if (kt < 3) { loadA((kt+1)&1, kt+1); CPA_COMMIT; }
        int st = kt & 1;
        #pragma unroll
        for (int ks = 0; ks < 2; ks++) {
            unsigned a[2][4], b[8][2];
            #pragma unroll
            for (int mt = 0; mt < 2; mt++) {
                unsigned addr = aBase + (unsigned)(st*128*80 + (wm*32 + mt*16)*80 + ks*32) + aLane;
                LDSM4(a[mt][0], a[mt][1], a[mt][2], a[mt][3], addr);
            }
            #pragma unroll
            for (int np = 0; np < 4; np++) {
                unsigned addr = bBase + (unsigned)((wn*64 + np*16)*272 + kt*64 + ks*32) + bLane;
                LDSM4(b[2*np][0], b[2*np][1], b[2*np+1][0], b[2*np+1][1], addr);
            }
            #pragma unroll
            for (int mt = 0; mt < 2; mt++)
                #pragma unroll
                for (int nt = 0; nt < 8; nt++)
                    mma16(acc[mt][nt], a[mt], b[nt]);
        }
    }
    #pragma unroll
    for (int mt = 0; mt < 2; mt++)
        #pragma unroll
        for (int hf = 0; hf < 2; hf++) {
            int i = ib + wm*32 + mt*16 + lrow + hf*8;
            size_t row = (size_t)i*L + n;
            #pragma unroll
            for (int nt = 0; nt < 8; nt++) {
                int c = wn*64 + nt*8 + 2*lq;
                *(float2*)(out + row*DP + c) =
                    make_float2(acc[mt][nt][hf*2]   + bout[c],
                                acc[mt][nt][hf*2+1] + bout[c+1]);
            }
        }
}

// ---------------- launch ----------------
extern "C" void kernel_launch(void* const* d_in, const int* in_sizes, int n_in,
                              void* d_out, int out_size)
{
    const float* pair    = (const float*)d_in[0];
    const float* bias    = (const float*)d_in[1];
    const float* gamma_p = (const float*)d_in[2];
    const float* beta_p  = (const float*)d_in[3];
    const float* gamma_b = (const float*)d_in[4];
    const float* beta_b  = (const float*)d_in[5];
    const float* Wq      = (const float*)d_in[6];
    const float* Wk      = (const float*)d_in[7];
    const float* Wv      = (const float*)d_in[8];
    const float* Wb      = (const float*)d_in[9];
    const float* Wg      = (const float*)d_in[10];
    const float* bg      = (const float*)d_in[11];
    const float* Wout    = (const float*)d_in[12];
    const float* bout    = (const float*)d_in[13];
    float* out = (float*)d_out;

    const int smProj = 128*136*2 + 2*128*136*2;      // 104448
    const int smQK   = 2 * (2*2*128*40) * 2;         // 81920
    const int smO    = (2*2*128*40 + 2*64*136) * 2;  // 75776
    const int smOut  = 2*128*40*2 + 128*136*2;       // 55296

    static cudaStream_t s1;
    static cudaEvent_t evFork, evPrep, evBias, evQK0, evVG;
    static int inited = 0;
    if (!inited) {
        cudaFuncSetAttribute(k_projQK, cudaFuncAttributeMaxDynamicSharedMemorySize, smProj);
        cudaFuncSetAttribute(k_projVG, cudaFuncAttributeMaxDynamicSharedMemorySize, smProj);
        cudaFuncSetAttribute(k_qk,     cudaFuncAttributeMaxDynamicSharedMemorySize, smQK);
        cudaFuncSetAttribute(k_o,      cudaFuncAttributeMaxDynamicSharedMemorySize, smO);
        cudaFuncSetAttribute(k_out,    cudaFuncAttributeMaxDynamicSharedMemorySize, smOut);
        cudaStreamCreateWithFlags(&s1, cudaStreamNonBlocking);
        cudaEventCreateWithFlags(&evFork, cudaEventDisableTiming);
        cudaEventCreateWithFlags(&evPrep, cudaEventDisableTiming);
        cudaEventCreateWithFlags(&evBias, cudaEventDisableTiming);
        cudaEventCreateWithFlags(&evQK0,  cudaEventDisableTiming);
        cudaEventCreateWithFlags(&evVG,   cudaEventDisableTiming);
        inited = 1;
    }

    // side stream: prep, then bias
    cudaEventRecord(evFork, 0);
    cudaStreamWaitEvent(s1, evFork, 0);
    k_prep    <<<320, 256, 0, s1>>>(Wq, Wk, Wv, Wg, Wout);
    cudaEventRecord(evPrep, s1);
    k_bias    <<<LL/8, 256, 0, s1>>>(bias, gamma_b, beta_b, Wb);
    cudaEventRecord(evBias, s1);

    // main: LN + Q,K projections, then QK logits
    cudaStreamWaitEvent(0, evPrep, 0);
    k_projQK  <<<LL/128, 256, smProj>>>(pair, gamma_p, beta_p);
    cudaEventRecord(evQK0, 0);
    k_qk      <<<dim3(3, 3, NH*SPLIT), 256, smQK>>>();

    // side: V + gate projections overlap with QK logits
    cudaStreamWaitEvent(s1, evQK0, 0);
    k_projVG  <<<LL/128, 256, smProj, s1>>>(bg);
    cudaEventRecord(evVG, s1);

    cudaStreamWaitEvent(0, evBias, 0);
    k_softmax <<<dim3(L, NH), 128>>>();
    cudaStreamWaitEvent(0, evVG, 0);
    k_o       <<<dim3(3, ND/128, NH), 256, smO>>>();
    k_out     <<<LL/128, 256, smOut>>>(bout, out);
}